// round 17
// baseline (speedup 1.0000x reference)
#include <cuda_runtime.h>
#include <cstdint>

typedef unsigned int u32;
typedef unsigned long long u64;

#define NQ    256
#define DIM   128
#define NBANK 500000
#define TOPK  32

#define TM    64          // q rows per block
#define TN    128         // n rows per block
#define KS    16          // K slice per stage (8 stages, double-buffered)
#define NST   (DIM / KS)  // 8
#define GT    256
#define PADK  20          // KS + 4 floats pad (bank-conflict-free for 16B ops)
#define CAP   4096        // per-query candidate capacity

// -------- device scratch (device-code-referenced ONLY; R12 lesson) ---------
__device__ float g_newctx[NQ * DIM];
__device__ int   g_cixs[NQ * TOPK];
__device__ float g_tau[NQ];
__device__ u32   g_cnt[NQ];
__device__ u64   g_cand[(size_t)NQ * CAP];     // 8 MB

// ---------------------------------------------------------------------------
__device__ __forceinline__ u64 mkkey(float v, u32 n) {
    u32 u = __float_as_uint(v);
    u = (u & 0x80000000u) ? ~u : (u | 0x80000000u);   // monotonic float key
    return ((u64)u << 32) | (u32)(~n);                // ties: smaller idx wins
}
__device__ __forceinline__ void ffma2(u64& d, u64 a, u64 b) {
    asm("fma.rn.f32x2 %0, %1, %2, %0;" : "+l"(d) : "l"(a), "l"(b));
}
__device__ __forceinline__ void cpasync16(u32 smem_dst, const void* gsrc, int src_bytes) {
    asm volatile("cp.async.cg.shared.global [%0], [%1], 16, %2;"
                 :: "r"(smem_dst), "l"(gsrc), "r"(src_bytes) : "memory");
}
__device__ __forceinline__ void cpasync_commit() {
    asm volatile("cp.async.commit_group;" ::: "memory");
}
__device__ __forceinline__ void cpasync_wait0() {
    asm volatile("cp.async.wait_group 0;" ::: "memory");
}

// ---------------------------------------------------------------------------
// Per-query threshold tau = 3*||A_q|| and candidate-count reset. 128 threads.
__global__ void prep_kernel(const float* __restrict__ Aparam, int useNewCtx)
{
    const float* A = useNewCtx ? g_newctx : Aparam;
    const int q = blockIdx.x, d = threadIdx.x;
    __shared__ float s[4];
    float x = A[(size_t)q * DIM + d];
    float v = x * x;
    #pragma unroll
    for (int off = 16; off; off >>= 1) v += __shfl_down_sync(0xffffffffu, v, off);
    if ((d & 31) == 0) s[d >> 5] = v;
    __syncthreads();
    if (d == 0) {
        g_tau[q] = 3.0f * sqrtf(s[0] + s[1] + s[2] + s[3]);
        g_cnt[q] = 0u;
    }
}

// ---------------------------------------------------------------------------
// GEMM with fused candidate filter. Double-buffered cp.async pipeline:
// stage s+1 loads overlap stage s compute; one __syncthreads per stage.
__global__ __launch_bounds__(GT, 2)
void gemm_kernel(const float* __restrict__ Aparam, const float* __restrict__ B,
                 int n_rows, int useNewCtx)
{
    __shared__ float Af[2][TM * PADK];   // 10.2 KB
    __shared__ float Bf[2][TN * PADK];   // 20.5 KB  (total 30.7 KB static)

    const float* A = useNewCtx ? g_newctx : Aparam;

    const int tid  = threadIdx.x;
    const int lane = tid & 31;
    const int w    = tid >> 5;
    const int n0   = blockIdx.x * TN;
    const int q0   = blockIdx.y * TM;

    const u32 afb = (u32)__cvta_generic_to_shared(&Af[0][0]);
    const u32 bfb = (u32)__cvta_generic_to_shared(&Bf[0][0]);

    // issue_stage(s, buf): A slice 64x16, B slice 128x16 (zero-fill past n_rows)
    auto issue_stage = [&](int s, int buf) {
        const int kb = s * KS;
        {   // A: 256 float4 slots, 1 per thread
            int r = tid >> 2, c4 = tid & 3;
            u32 dst = afb + (u32)((buf * TM * PADK + r * PADK + 4 * c4) * 4);
            cpasync16(dst, A + (size_t)(q0 + r) * DIM + kb + 4 * c4, 16);
        }
        #pragma unroll
        for (int it = 0; it < 2; ++it) {   // B: 512 float4 slots, 2 per thread
            int idx = tid + GT * it;
            int r = idx >> 2, c4 = idx & 3;
            int gn = n0 + r;
            int ok = (gn < n_rows);
            u32 dst = bfb + (u32)((buf * TN * PADK + r * PADK + 4 * c4) * 4);
            cpasync16(dst, B + (size_t)(ok ? gn : 0) * DIM + kb + 4 * c4, ok ? 16 : 0);
        }
        cpasync_commit();
    };

    u64 acc[8][4];
    #pragma unroll
    for (int i = 0; i < 8; ++i)
        #pragma unroll
        for (int j = 0; j < 4; ++j) acc[i][j] = 0ull;

    issue_stage(0, 0);

    for (int s = 0; s < NST; ++s) {
        const int buf = s & 1;
        cpasync_wait0();
        __syncthreads();               // stage s ready; all warps past stage s-1
        if (s + 1 < NST) issue_stage(s + 1, buf ^ 1);

        #pragma unroll
        for (int k4 = 0; k4 < KS / 4; ++k4) {
            ulonglong2 b[4];
            #pragma unroll
            for (int j = 0; j < 4; ++j)
                b[j] = *(const ulonglong2*)(&Bf[buf][(lane + 32 * j) * PADK + 4 * k4]);
            #pragma unroll
            for (int i = 0; i < 8; ++i) {
                ulonglong2 a = *(const ulonglong2*)(&Af[buf][(w * 8 + i) * PADK + 4 * k4]);
                #pragma unroll
                for (int j = 0; j < 4; ++j) {
                    ffma2(acc[i][j], a.x, b[j].x);
                    ffma2(acc[i][j], a.y, b[j].y);
                }
            }
        }
        __syncthreads();               // all warps done reading buf before reuse
    }

    // epilogue: horizontal add + threshold filter (expected ~4 hits/block)
    #pragma unroll
    for (int i = 0; i < 8; ++i) {
        const int q = q0 + w * 8 + i;
        const float tau = g_tau[q];
        #pragma unroll
        for (int j = 0; j < 4; ++j) {
            float lo = __uint_as_float((u32)(acc[i][j] & 0xffffffffu));
            float hi = __uint_as_float((u32)(acc[i][j] >> 32));
            float v  = lo + hi;
            int   gn = n0 + lane + 32 * j;
            if (v > tau && gn < n_rows) {
                u32 pos = atomicAdd(&g_cnt[q], 1u);
                if (pos < CAP) g_cand[(size_t)q * CAP + pos] = mkkey(v, (u32)gn);
            }
        }
    }
}

// ---------------------------------------------------------------------------
// Exact per-query top-32 from candidates; full-recompute fallback if the
// threshold path can't guarantee exactness (cnt<32 or overflow). 256 threads.
__global__ __launch_bounds__(256)
void final_topk(const float* __restrict__ Aparam, const float* __restrict__ B,
                float* __restrict__ outFloat, int useCixs, int useNewCtx)
{
    const int q   = blockIdx.x;
    const int tid = threadIdx.x;
    const u32 cnt = g_cnt[q];

    __shared__ u64 red[256];

    if (cnt >= TOPK && cnt <= CAP) {
        u64 mine[CAP / 256];
        int m = 0;
        for (u32 i = tid; i < cnt; i += 256) mine[m++] = g_cand[(size_t)q * CAP + i];

        for (int r = 0; r < TOPK; ++r) {
            u64 mymax = 0ull; int mp = -1;
            for (int jj = 0; jj < m; ++jj)
                if (mine[jj] > mymax) { mymax = mine[jj]; mp = jj; }
            red[tid] = mymax;
            __syncthreads();
            for (int s = 128; s > 0; s >>= 1) {
                if (tid < s) { u64 o = red[tid + s]; if (o > red[tid]) red[tid] = o; }
                __syncthreads();
            }
            u64 win = red[0];
            __syncthreads();
            if (mp >= 0 && mymax == win) mine[mp] = 0ull;  // unique keys
            if (tid == 0) {
                int idx = (int)(~(u32)(win & 0xffffffffu));
                if (useCixs) g_cixs[q * TOPK + r] = idx;
                else         outFloat[q * TOPK + r] = (float)idx;
            }
            __syncthreads();
        }
    } else {
        // fallback (exactness safety; statistically never taken)
        __shared__ float qrow[DIM];
        const float* A = useNewCtx ? g_newctx : Aparam;
        for (int d = tid; d < DIM; d += 256) qrow[d] = A[(size_t)q * DIM + d];
        __syncthreads();

        u64 loc[TOPK];
        #pragma unroll
        for (int j = 0; j < TOPK; ++j) loc[j] = 0ull;
        u64 kmin = 0ull; int minpos = 0;

        for (int n = tid; n < NBANK; n += 256) {
            const float4* br = (const float4*)(B + (size_t)n * DIM);
            float s = 0.f;
            #pragma unroll
            for (int c = 0; c < DIM / 4; ++c) {
                float4 b = br[c];
                s += qrow[4 * c] * b.x + qrow[4 * c + 1] * b.y
                   + qrow[4 * c + 2] * b.z + qrow[4 * c + 3] * b.w;
            }
            u64 key = mkkey(s, (u32)n);
            if (key > kmin) {
                loc[minpos] = key;
                kmin = loc[0]; minpos = 0;
                #pragma unroll
                for (int j = 1; j < TOPK; ++j)
                    if (loc[j] < kmin) { kmin = loc[j]; minpos = j; }
            }
        }
        for (int r = 0; r < TOPK; ++r) {
            u64 mymax = loc[0]; int mp = 0;
            #pragma unroll
            for (int j = 1; j < TOPK; ++j)
                if (loc[j] > mymax) { mymax = loc[j]; mp = j; }
            red[tid] = mymax;
            __syncthreads();
            for (int s = 128; s > 0; s >>= 1) {
                if (tid < s) { u64 o = red[tid + s]; if (o > red[tid]) red[tid] = o; }
                __syncthreads();
            }
            u64 win = red[0];
            __syncthreads();
            if (mymax == win) loc[mp] = 0ull;
            if (tid == 0) {
                int idx = (int)(~(u32)(win & 0xffffffffu));
                if (useCixs) g_cixs[q * TOPK + r] = idx;
                else         outFloat[q * TOPK + r] = (float)idx;
            }
            __syncthreads();
        }
    }
}

// ---------------------------------------------------------------------------
__global__ void mean_kernel(const float* __restrict__ bank)
{
    const int q = blockIdx.x;
    const int d = threadIdx.x;
    float s = 0.f;
    #pragma unroll
    for (int j = 0; j < TOPK; ++j)
        s += bank[(size_t)g_cixs[q * TOPK + j] * DIM + d];
    g_newctx[q * DIM + d] = s * (1.0f / 32.0f);
}

// ---------------------------------------------------------------------------
extern "C" void kernel_launch(void* const* d_in, const int* in_sizes, int n_in,
                              void* d_out, int out_size)
{
    // Inputs by element count; same-size banks in appearance order =
    // setup_inputs dict order: contexts, enc_ans, enc_ctx, k. (Proven R13.)
    const float* contexts = nullptr;
    const float* enc_ans  = nullptr;
    const float* enc_ctx  = nullptr;
    for (int i = 0; i < n_in; ++i) {
        if (in_sizes[i] == NQ * DIM) {
            contexts = (const float*)d_in[i];
        } else if (in_sizes[i] == NBANK * DIM) {
            if (!enc_ans) enc_ans = (const float*)d_in[i];
            else          enc_ctx = (const float*)d_in[i];
        }
    }
    if (!contexts && n_in >= 1) contexts = (const float*)d_in[0];
    if (!enc_ans  && n_in >= 2) enc_ans  = (const float*)d_in[1];
    if (!enc_ctx  && n_in >= 3) enc_ctx  = (const float*)d_in[2];

    dim3 ggrid((NBANK + TN - 1) / TN, NQ / TM);

    // Hop 1: contexts vs context bank -> candidates -> g_cixs
    prep_kernel<<<NQ, DIM>>>(contexts, 0);
    gemm_kernel<<<ggrid, GT>>>(contexts, enc_ctx, NBANK, 0);
    final_topk<<<NQ, 256>>>(contexts, enc_ctx, nullptr, 1, 0);
    // Gather + mean -> g_newctx
    mean_kernel<<<NQ, DIM>>>(enc_ctx);
    // Hop 2: averaged contexts vs answer bank -> candidates -> d_out (float)
    prep_kernel<<<NQ, DIM>>>(nullptr, 1);
    gemm_kernel<<<ggrid, GT>>>(nullptr, enc_ans, NBANK, 1);
    final_topk<<<NQ, 256>>>(nullptr, enc_ans, (float*)d_out, 0, 1);
}